// round 16
// baseline (speedup 1.0000x reference)
#include <cuda_runtime.h>
#include <cuda_bf16.h>
#include <cstdint>

#define BATCH  512
#define N_NODE 200
#define C_IN   200
#define HIDDEN 128

typedef unsigned long long ull;

// ===================== PTX helpers =====================
__device__ __forceinline__ uint32_t smem_u32(const void* p) {
    uint32_t a;
    asm("{ .reg .u64 t; cvta.to.shared.u64 t, %1; cvt.u32.u64 %0, t; }"
        : "=r"(a) : "l"(p));
    return a;
}

#define LDSM_X4(r0, r1, r2, r3, addr) \
    asm volatile("ldmatrix.sync.aligned.m8n8.x4.shared.b16 {%0,%1,%2,%3}, [%4];" \
        : "=r"(r0), "=r"(r1), "=r"(r2), "=r"(r3) : "r"(addr))

#define LDSM_X4T(r0, r1, r2, r3, addr) \
    asm volatile("ldmatrix.sync.aligned.m8n8.x4.trans.shared.b16 {%0,%1,%2,%3}, [%4];" \
        : "=r"(r0), "=r"(r1), "=r"(r2), "=r"(r3) : "r"(addr))

#define MMA16816(c, a0, a1, a2, a3, b0, b1) \
    asm volatile("mma.sync.aligned.m16n8k16.row.col.f32.bf16.bf16.f32 " \
        "{%0,%1,%2,%3}, {%4,%5,%6,%7}, {%8,%9}, {%0,%1,%2,%3};" \
        : "+f"((c)[0]), "+f"((c)[1]), "+f"((c)[2]), "+f"((c)[3]) \
        : "r"(a0), "r"(a1), "r"(a2), "r"(a3), "r"(b0), "r"(b1))

#define CP_ASYNC16(dst, src) \
    asm volatile("cp.async.cg.shared.global [%0], [%1], 16;" \
        :: "r"(dst), "l"(src) : "memory")
#define CP_ASYNC_WAIT_ALL() \
    asm volatile("cp.async.commit_group;\n\tcp.async.wait_group 0;" ::: "memory")

__device__ __forceinline__ void split2(float a, float b, uint32_t& hp, uint32_t& lp) {
    __nv_bfloat16 h0 = __float2bfloat16(a);
    __nv_bfloat16 h1 = __float2bfloat16(b);
    __nv_bfloat16 l0 = __float2bfloat16(a - __bfloat162float(h0));
    __nv_bfloat16 l1 = __float2bfloat16(b - __bfloat162float(h1));
    hp = (uint32_t)__bfloat16_as_ushort(h0) | ((uint32_t)__bfloat16_as_ushort(h1) << 16);
    lp = (uint32_t)__bfloat16_as_ushort(l0) | ((uint32_t)__bfloat16_as_ushort(l1) << 16);
}

// W1 pre-split into bf16 hi/lo, zero-padded to K=208 rows: [208][128]
__device__ __nv_bfloat16 g_w1hi[208 * HIDDEN];
__device__ __nv_bfloat16 g_w1lo[208 * HIDDEN];

// ---------------------------------------------------------------------------
// K0: split W1 fp32 -> bf16 hi/lo with zero k-padding (runs once, tiny)
// ---------------------------------------------------------------------------
__global__ void split_w1_kernel(const float* __restrict__ W1)
{
    int idx = blockIdx.x * 256 + threadIdx.x;
    if (idx >= 208 * HIDDEN) return;
    int k = idx / HIDDEN;
    float v = (k < C_IN) ? W1[idx] : 0.f;
    __nv_bfloat16 h = __float2bfloat16(v);
    __nv_bfloat16 l = __float2bfloat16(v - __bfloat162float(h));
    g_w1hi[idx] = h;
    g_w1lo[idx] = l;
}

// ---------------------------------------------------------------------------
// FUSED kernel: one CTA per batch, 512 threads.
//   Phase 1: xw = x[b] @ W1 (split-bf16, 3 products), A streamed in k16
//            chunks (double-buffered), result stored to smem (over W1).
//            Warps 14-15 concurrently stage adj rows 95..198 + degrees.
//   Phase 2: agg = adjT @ xw (split-bf16 B, exact A), fused GIN epilogue.
// ---------------------------------------------------------------------------
// smem layout
#define CH_PITCH   48
#define CH0_HI     0                   // 208*48 = 9984 each
#define CH0_LO     9984
#define CH1_HI     19968
#define CH1_LO     29952               // chunk region ends 39936 (+tail pad 768)
#define PITCH_A    432                 // phase-2 adjT tile pitch
#define OFF_A      0                   // 208*432 = 89856 (rows 0..94 overlap chunks)
#define PITCH_B    272
#define OFF_BHI    89856               // W1 (phase 1) -> xw (phase 2)
#define OFF_BLO    146432              // + 56576
#define OFF_DEG    203008              // 200 floats
#define OFF_WS     203808              // 14*2 floats (pad 128)
#define OFF_B1S    203936              // 128 floats
#define OFF_W2S    204448              // 256 floats
#define SMEM_TOTAL 205504

__global__ __launch_bounds__(512, 1) void gin_fused_all_kernel(
    const float* __restrict__ x,
    const int*   __restrict__ adj,
    const float* __restrict__ b1,
    const float* __restrict__ W2,
    const float* __restrict__ b2,
    const float* __restrict__ eps1p,
    const float* __restrict__ eps2p,
    float*       __restrict__ out)
{
    extern __shared__ char smem[];
    const uint32_t sbase = smem_u32(smem);
    float* degs = (float*)(smem + OFF_DEG);
    float* wsum = (float*)(smem + OFF_WS);
    float* b1s  = (float*)(smem + OFF_B1S);
    float* w2s  = (float*)(smem + OFF_W2S);

    const int b    = blockIdx.x;
    const int t    = threadIdx.x;
    const int w    = t >> 5;
    const int lane = t & 31;
    const float* xb = x + (size_t)b * N_NODE * C_IN;
    const int* adj_b = adj + (size_t)b * N_NODE * N_NODE;

    // ---- issue W1 cp.async (B of phase 1) ----
    for (int idx = t; idx < 208 * 16; idx += 512) {
        const int r = idx >> 4;
        const int c = idx & 15;
        CP_ASYNC16(sbase + OFF_BHI + r * PITCH_B + c * 16,
                   (const char*)g_w1hi + r * 256 + c * 16);
        CP_ASYNC16(sbase + OFF_BLO + r * PITCH_B + c * 16,
                   (const char*)g_w1lo + r * 256 + c * 16);
    }

    // ---- zero chunk pad rows (200..207 x 4 buffers) + overflow tail ----
    {
        const uint4 z = make_uint4(0u, 0u, 0u, 0u);
        for (int idx = t; idx < 96; idx += 512) {
            const int buf = idx / 24;
            const int rr  = (idx % 24) / 3;
            const int c   = idx % 3;
            *(uint4*)(smem + buf * 9984 + (200 + rr) * CH_PITCH + c * 16) = z;
        }
        for (int idx = t; idx < 48; idx += 512)
            *(uint4*)(smem + 39936 + idx * 16) = z;
        if (t < 128) b1s[t] = b1[t];
        if (t < 256) w2s[t] = W2[t];
    }

    // ---- stage chunk 0 (k = 0..15) ----
    {
        for (int idx = t; idx < 800; idx += 512) {
            const int m = idx >> 2, q = idx & 3;
            float4 v = *(const float4*)&xb[m * C_IN + 4 * q];   // k<16 always valid
            uint2 hp, lp;
            split2(v.x, v.y, hp.x, lp.x);
            split2(v.z, v.w, hp.y, lp.y);
            *(uint2*)(smem + CH0_HI + m * CH_PITCH + q * 8) = hp;
            *(uint2*)(smem + CH0_LO + m * CH_PITCH + q * 8) = lp;
        }
    }
    CP_ASYNC_WAIT_ALL();
    __syncthreads();

    // ---- phase 1: xw = x @ W1, warp = (mp = w%7: m32) x (nh = w/7: n64) ----
    // warps 14,15: stage adj rows 95..198 (8 per iteration) during MMA.
    const int mp = (w < 14) ? (w % 7) : 0;
    const int nh = (w < 14) ? (w / 7) : 0;
    const int g  = lane >> 2;
    const int tg = lane & 3;

    float acc[2][8][4];
#pragma unroll
    for (int mt = 0; mt < 2; mt++)
#pragma unroll
        for (int n = 0; n < 8; n++) {
            acc[mt][n][0] = 0.f; acc[mt][n][1] = 0.f;
            acc[mt][n][2] = 0.f; acc[mt][n][3] = 0.f;
        }

    const uint32_t a_lane = (uint32_t)(32 * mp + (lane & 15)) * CH_PITCH
                          + (uint32_t)(lane >> 4) * 16;
    const uint32_t b_lane = (uint32_t)(lane & 15) * PITCH_B
                          + (uint32_t)(lane >> 4) * 16 + (uint32_t)nh * 128;

#pragma unroll 1
    for (int ks = 0; ks < 13; ks++) {
        // prefetch next chunk (LDGs issue before MMA; uses after)
        float4 v0, v1;
        const int has1 = (t < 288);
        if (ks < 12) {
            const int k0n = 16 * (ks + 1);
            {
                const int m = t >> 2, q = t & 3, k = k0n + 4 * q;
                v0 = (k < 200) ? *(const float4*)&xb[m * C_IN + k]
                               : make_float4(0.f, 0.f, 0.f, 0.f);
            }
            if (has1) {
                const int idx = t + 512;
                const int m = idx >> 2, q = idx & 3, k = k0n + 4 * q;
                v1 = (k < 200) ? *(const float4*)&xb[m * C_IN + k]
                               : make_float4(0.f, 0.f, 0.f, 0.f);
            }
        }

        if (w < 14) {
            // MMA on current buffer
            const uint32_t ch_hi = sbase + ((ks & 1) ? CH1_HI : CH0_HI) + a_lane;
            const uint32_t ch_lo = ch_hi + 9984;
            uint32_t ah[2][4], al[2][4];
            LDSM_X4(ah[0][0], ah[0][1], ah[0][2], ah[0][3], ch_hi);
            LDSM_X4(ah[1][0], ah[1][1], ah[1][2], ah[1][3], ch_hi + 16 * CH_PITCH);
            LDSM_X4(al[0][0], al[0][1], al[0][2], al[0][3], ch_lo);
            LDSM_X4(al[1][0], al[1][1], al[1][2], al[1][3], ch_lo + 16 * CH_PITCH);
            const uint32_t brow = sbase + OFF_BHI + b_lane + (uint32_t)ks * 16 * PITCH_B;
#pragma unroll
            for (int nbg = 0; nbg < 4; nbg++) {
                uint32_t h0, h1, h2, h3, l0, l1, l2, l3;
                LDSM_X4T(h0, h1, h2, h3, brow + (uint32_t)nbg * 32);
#pragma unroll
                for (int mt = 0; mt < 2; mt++) {
                    MMA16816(acc[mt][2 * nbg],     ah[mt][0], ah[mt][1], ah[mt][2], ah[mt][3], h0, h1);
                    MMA16816(acc[mt][2 * nbg + 1], ah[mt][0], ah[mt][1], ah[mt][2], ah[mt][3], h2, h3);
                    MMA16816(acc[mt][2 * nbg],     al[mt][0], al[mt][1], al[mt][2], al[mt][3], h0, h1);
                    MMA16816(acc[mt][2 * nbg + 1], al[mt][0], al[mt][1], al[mt][2], al[mt][3], h2, h3);
                }
                LDSM_X4T(l0, l1, l2, l3,
                         brow + (uint32_t)(OFF_BLO - OFF_BHI) + (uint32_t)nbg * 32);
#pragma unroll
                for (int mt = 0; mt < 2; mt++) {
                    MMA16816(acc[mt][2 * nbg],     ah[mt][0], ah[mt][1], ah[mt][2], ah[mt][3], l0, l1);
                    MMA16816(acc[mt][2 * nbg + 1], ah[mt][0], ah[mt][1], ah[mt][2], ah[mt][3], l2, l3);
                }
            }
        } else {
            // warps 14,15: stage adj rows 95+8ks+(w-14)*4 .. +3 (rows 95..198)
            const int rbase = 95 + 8 * ks + (w - 14) * 4;
#pragma unroll
            for (int rr = 0; rr < 4; rr++) {
                const int i = rbase + rr;                 // 95..198, always <200
                const int* row = &adj_b[i * N_NODE];
                char* dst = smem + OFF_A + i * PITCH_A;
                int rsum = 0;
#pragma unroll
                for (int c = 0; c < 7; c++) {
                    const int j = lane + 32 * c;
                    if (j < N_NODE) {
                        int v = row[j];
                        *(unsigned short*)(dst + j * 2) =
                            v ? (unsigned short)0x3F80u : (unsigned short)0u;
                        rsum += v;
                    }
                }
#pragma unroll
                for (int off = 16; off; off >>= 1)
                    rsum += __shfl_xor_sync(0xffffffffu, rsum, off);
                if (lane == 0) degs[i] = (float)rsum;
                if (lane < 2)                            // col pad bytes 400..431
                    *(uint4*)(dst + 400 + lane * 16) = make_uint4(0u, 0u, 0u, 0u);
            }
        }

        // store prefetched chunk
        if (ks < 12) {
            const int bofs = ((ks + 1) & 1) ? CH1_HI : CH0_HI;
            {
                const int m = t >> 2, q = t & 3;
                uint2 hp, lp;
                split2(v0.x, v0.y, hp.x, lp.x);
                split2(v0.z, v0.w, hp.y, lp.y);
                *(uint2*)(smem + bofs + m * CH_PITCH + q * 8) = hp;
                *(uint2*)(smem + bofs + 9984 + m * CH_PITCH + q * 8) = lp;
            }
            if (has1) {
                const int idx = t + 512;
                const int m = idx >> 2, q = idx & 3;
                uint2 hp, lp;
                split2(v1.x, v1.y, hp.x, lp.x);
                split2(v1.z, v1.w, hp.y, lp.y);
                *(uint2*)(smem + bofs + m * CH_PITCH + q * 8) = hp;
                *(uint2*)(smem + bofs + 9984 + m * CH_PITCH + q * 8) = lp;
            }
        }
        __syncthreads();
    }

    // ---- store xw fragments (bf16 hi/lo) into former W1 region ----
    if (w < 14) {
#pragma unroll
        for (int mt = 0; mt < 2; mt++) {
            const int ra = 32 * mp + 16 * mt + g;
            const int rb = ra + 8;
#pragma unroll
            for (int nt = 0; nt < 8; nt++) {
                const int f = 64 * nh + nt * 8 + tg * 2;
                uint32_t hp, lp;
                if (ra < 208) {
                    split2(acc[mt][nt][0], acc[mt][nt][1], hp, lp);
                    *(uint32_t*)(smem + OFF_BHI + ra * PITCH_B + f * 2) = hp;
                    *(uint32_t*)(smem + OFF_BLO + ra * PITCH_B + f * 2) = lp;
                }
                if (rb < 208) {
                    split2(acc[mt][nt][2], acc[mt][nt][3], hp, lp);
                    *(uint32_t*)(smem + OFF_BHI + rb * PITCH_B + f * 2) = hp;
                    *(uint32_t*)(smem + OFF_BLO + rb * PITCH_B + f * 2) = lp;
                }
            }
        }
    }

    // ---- stage remaining adj rows (0..94, 199) + A pad rows 200..207 ----
    {
        const uint4 z = make_uint4(0u, 0u, 0u, 0u);
        for (int idx = t; idx < 8 * 27; idx += 512) {
            const int r = 200 + idx / 27;
            const int c = idx % 27;
            *(uint4*)(smem + OFF_A + r * PITCH_A + c * 16) = z;
        }
        for (int idx8 = w; idx8 < 96; idx8 += 16) {
            const int i = (idx8 < 95) ? idx8 : 199;
            const int* row = &adj_b[i * N_NODE];
            char* dst = smem + OFF_A + i * PITCH_A;
            int rsum = 0;
#pragma unroll
            for (int c = 0; c < 7; c++) {
                const int j = lane + 32 * c;
                if (j < N_NODE) {
                    int v = row[j];
                    *(unsigned short*)(dst + j * 2) =
                        v ? (unsigned short)0x3F80u : (unsigned short)0u;
                    rsum += v;
                }
            }
#pragma unroll
            for (int off = 16; off; off >>= 1)
                rsum += __shfl_xor_sync(0xffffffffu, rsum, off);
            if (lane == 0) degs[i] = (float)rsum;
            if (lane < 2)
                *(uint4*)(dst + 400 + lane * 16) = z;
        }
    }
    __syncthreads();

    // ---- phase 2 MMA: agg = adjT @ xw (warps 0..13, m32 x n64) ----
    if (w < 14) {
#pragma unroll
        for (int mt = 0; mt < 2; mt++)
#pragma unroll
            for (int n = 0; n < 8; n++) {
                acc[mt][n][0] = 0.f; acc[mt][n][1] = 0.f;
                acc[mt][n][2] = 0.f; acc[mt][n][3] = 0.f;
            }

        const uint32_t a_row = (uint32_t)((lane & 7) + ((lane >> 4) << 3)) * PITCH_A;
        const uint32_t a0_base = sbase + OFF_A + a_row
            + (uint32_t)(32 * mp + ((lane >> 3) & 1) * 8) * 2;
        const uint32_t a1_base = a0_base + 32;
        const uint32_t bhi_base = sbase + OFF_BHI + b_lane;
        const uint32_t blo_base = sbase + OFF_BLO + b_lane;

#pragma unroll 1
        for (int ks = 0; ks < 13; ks++) {
            const uint32_t adelta = (uint32_t)ks * 16 * PITCH_A;
            uint32_t a[2][4];
            LDSM_X4T(a[0][0], a[0][1], a[0][2], a[0][3], a0_base + adelta);
            LDSM_X4T(a[1][0], a[1][1], a[1][2], a[1][3], a1_base + adelta);
            const uint32_t brow = (uint32_t)ks * 16 * PITCH_B;
#pragma unroll
            for (int nbg = 0; nbg < 4; nbg++) {
                uint32_t h0, h1, h2, h3, l0, l1, l2, l3;
                LDSM_X4T(h0, h1, h2, h3, bhi_base + brow + (uint32_t)nbg * 32);
#pragma unroll
                for (int mt = 0; mt < 2; mt++) {
                    MMA16816(acc[mt][2 * nbg],     a[mt][0], a[mt][1], a[mt][2], a[mt][3], h0, h1);
                    MMA16816(acc[mt][2 * nbg + 1], a[mt][0], a[mt][1], a[mt][2], a[mt][3], h2, h3);
                }
                LDSM_X4T(l0, l1, l2, l3, blo_base + brow + (uint32_t)nbg * 32);
#pragma unroll
                for (int mt = 0; mt < 2; mt++) {
                    MMA16816(acc[mt][2 * nbg],     a[mt][0], a[mt][1], a[mt][2], a[mt][3], l0, l1);
                    MMA16816(acc[mt][2 * nbg + 1], a[mt][0], a[mt][1], a[mt][2], a[mt][3], l2, l3);
                }
            }
        }

        // ---- epilogue ----
        const float c1x = 1.f + *eps1p;
        const float c2x = 1.f + *eps2p;

        float s0 = 0.f, s1 = 0.f;
#pragma unroll
        for (int mt = 0; mt < 2; mt++) {
#pragma unroll
            for (int half = 0; half < 2; half++) {
                const int j = 32 * mp + 16 * mt + g + half * 8;
                const int jc = (j < N_NODE) ? j : (N_NODE - 1);
                float p0 = 0.f, p1 = 0.f;
#pragma unroll
                for (int nt = 0; nt < 8; nt++) {
                    const int f = 64 * nh + nt * 8 + tg * 2;
                    uint32_t hv = *(uint32_t*)(smem + OFF_BHI + jc * PITCH_B + f * 2);
                    uint32_t lv = *(uint32_t*)(smem + OFF_BLO + jc * PITCH_B + f * 2);
                    float x0 = __uint_as_float(hv << 16) + __uint_as_float(lv << 16);
                    float x1 = __uint_as_float(hv & 0xFFFF0000u)
                             + __uint_as_float(lv & 0xFFFF0000u);
                    float a0 = acc[mt][nt][2 * half + 0];
                    float a1 = acc[mt][nt][2 * half + 1];
                    float h0 = fmaxf(fmaf(c1x, x0, a0) + b1s[f], 0.f);
                    float h1 = fmaxf(fmaf(c1x, x1, a1) + b1s[f + 1], 0.f);
                    p0 += h0 * w2s[f * 2]     + h1 * w2s[(f + 1) * 2];
                    p1 += h0 * w2s[f * 2 + 1] + h1 * w2s[(f + 1) * 2 + 1];
                }
                float wj = (j < N_NODE) ? (c2x + degs[jc]) : 0.f;
                s0 += p0 * wj;
                s1 += p1 * wj;
            }
        }
#pragma unroll
        for (int off = 1; off <= 16; off <<= 1) {
            s0 += __shfl_xor_sync(0xffffffffu, s0, off);
            s1 += __shfl_xor_sync(0xffffffffu, s1, off);
        }
        if (lane == 0) { wsum[w * 2 + 0] = s0; wsum[w * 2 + 1] = s1; }
    }
    __syncthreads();

    if (t < 2) {
        float s = 0.f;
#pragma unroll
        for (int q = 0; q < 14; q++) s += wsum[q * 2 + t];
        out[b * 2 + t] = s * (1.f / N_NODE) + b2[t];
    }
}

// ---------------------------------------------------------------------------
extern "C" void kernel_launch(void* const* d_in, const int* in_sizes, int n_in,
                              void* d_out, int out_size)
{
    const float* x    = (const float*)d_in[0];   // [512,200,200]
    const int*   adj  = (const int*)  d_in[1];   // [512,200,200]
    const float* W1   = (const float*)d_in[2];   // [200,128]
    const float* b1   = (const float*)d_in[3];   // [128]
    const float* W2   = (const float*)d_in[4];   // [128,2]
    const float* b2   = (const float*)d_in[5];   // [2]
    const float* eps1 = (const float*)d_in[6];
    const float* eps2 = (const float*)d_in[7];
    float* out = (float*)d_out;                  // [512,2]

    cudaFuncSetAttribute(gin_fused_all_kernel,
                         cudaFuncAttributeMaxDynamicSharedMemorySize, SMEM_TOTAL);

    split_w1_kernel<<<(208 * HIDDEN + 255) / 256, 256>>>(W1);
    gin_fused_all_kernel<<<BATCH, 512, SMEM_TOTAL>>>(x, adj, b1, W2, b2,
                                                     eps1, eps2, out);
}

// round 17
// speedup vs baseline: 1.6456x; 1.6456x over previous
#include <cuda_runtime.h>
#include <cuda_bf16.h>
#include <cstdint>

#define BATCH  512
#define N_NODE 200
#define C_IN   200
#define HIDDEN 128

typedef unsigned long long ull;

// ===================== PTX helpers =====================
__device__ __forceinline__ uint32_t smem_u32(const void* p) {
    uint32_t a;
    asm("{ .reg .u64 t; cvta.to.shared.u64 t, %1; cvt.u32.u64 %0, t; }"
        : "=r"(a) : "l"(p));
    return a;
}

#define LDSM_X4(r0, r1, r2, r3, addr) \
    asm volatile("ldmatrix.sync.aligned.m8n8.x4.shared.b16 {%0,%1,%2,%3}, [%4];" \
        : "=r"(r0), "=r"(r1), "=r"(r2), "=r"(r3) : "r"(addr))

#define LDSM_X4T(r0, r1, r2, r3, addr) \
    asm volatile("ldmatrix.sync.aligned.m8n8.x4.trans.shared.b16 {%0,%1,%2,%3}, [%4];" \
        : "=r"(r0), "=r"(r1), "=r"(r2), "=r"(r3) : "r"(addr))

#define MMA16816(c, a0, a1, a2, a3, b0, b1) \
    asm volatile("mma.sync.aligned.m16n8k16.row.col.f32.bf16.bf16.f32 " \
        "{%0,%1,%2,%3}, {%4,%5,%6,%7}, {%8,%9}, {%0,%1,%2,%3};" \
        : "+f"((c)[0]), "+f"((c)[1]), "+f"((c)[2]), "+f"((c)[3]) \
        : "r"(a0), "r"(a1), "r"(a2), "r"(a3), "r"(b0), "r"(b1))

#define CP_ASYNC16(dst, src) \
    asm volatile("cp.async.cg.shared.global [%0], [%1], 16;" \
        :: "r"(dst), "l"(src) : "memory")
#define CP_ASYNC_WAIT_ALL() \
    asm volatile("cp.async.commit_group;\n\tcp.async.wait_group 0;" ::: "memory")

__device__ __forceinline__ void split2(float a, float b, uint32_t& hp, uint32_t& lp) {
    __nv_bfloat16 h0 = __float2bfloat16(a);
    __nv_bfloat16 h1 = __float2bfloat16(b);
    __nv_bfloat16 l0 = __float2bfloat16(a - __bfloat162float(h0));
    __nv_bfloat16 l1 = __float2bfloat16(b - __bfloat162float(h1));
    hp = (uint32_t)__bfloat16_as_ushort(h0) | ((uint32_t)__bfloat16_as_ushort(h1) << 16);
    lp = (uint32_t)__bfloat16_as_ushort(l0) | ((uint32_t)__bfloat16_as_ushort(l1) << 16);
}

// W1 pre-split into bf16 hi/lo, zero-padded to K=208 rows: [208][128]
__device__ __nv_bfloat16 g_w1hi[208 * HIDDEN];
__device__ __nv_bfloat16 g_w1lo[208 * HIDDEN];

// ---------------------------------------------------------------------------
// K0: split W1 fp32 -> bf16 hi/lo with zero k-padding (runs once, tiny)
// ---------------------------------------------------------------------------
__global__ void split_w1_kernel(const float* __restrict__ W1)
{
    int idx = blockIdx.x * 256 + threadIdx.x;
    if (idx >= 208 * HIDDEN) return;
    int k = idx / HIDDEN;
    float v = (k < C_IN) ? W1[idx] : 0.f;
    __nv_bfloat16 h = __float2bfloat16(v);
    __nv_bfloat16 l = __float2bfloat16(v - __bfloat162float(h));
    g_w1hi[idx] = h;
    g_w1lo[idx] = l;
}

// ---------------------------------------------------------------------------
// FUSED kernel: one CTA per batch, 512 threads.
//   Phase 1: xw = x[b] @ W1 (split-bf16, 3 products). A streamed in k16
//            chunks, 4 slots, prefetch distance 2, barrier every 2nd iter.
//   Phase 2: agg = adjT @ xw (split-bf16 B, exact A), fused GIN epilogue.
// ---------------------------------------------------------------------------
// smem layout
#define CH_PITCH   48
#define CH_SLOT    19968               // hi (9984) + lo (9984) per slot
                                       // 4 slots: 0..79872 (inside A region)
#define PITCH_A    432                 // phase-2 adjT tile pitch
#define OFF_A      0                   // 208*432 = 89856
#define PITCH_B    272
#define OFF_BHI    89856               // W1 (phase 1) -> xw (phase 2)
#define OFF_BLO    146432              // + 56576
#define OFF_DEG    203008              // 200 floats
#define OFF_WS     203808              // 14*2 floats (pad 128)
#define OFF_B1S    203936              // 128 floats
#define OFF_W2S    204448              // 256 floats
#define SMEM_TOTAL 205504

__global__ __launch_bounds__(512, 1) void gin_fused_all_kernel(
    const float* __restrict__ x,
    const int*   __restrict__ adj,
    const float* __restrict__ b1,
    const float* __restrict__ W2,
    const float* __restrict__ b2,
    const float* __restrict__ eps1p,
    const float* __restrict__ eps2p,
    float*       __restrict__ out)
{
    extern __shared__ char smem[];
    const uint32_t sbase = smem_u32(smem);
    float* degs = (float*)(smem + OFF_DEG);
    float* wsum = (float*)(smem + OFF_WS);
    float* b1s  = (float*)(smem + OFF_B1S);
    float* w2s  = (float*)(smem + OFF_W2S);

    const int b    = blockIdx.x;
    const int t    = threadIdx.x;
    const int w    = t >> 5;
    const int lane = t & 31;
    const float* xb = x + (size_t)b * N_NODE * C_IN;
    const int* adj_b = adj + (size_t)b * N_NODE * N_NODE;

    // ---- issue W1 cp.async (B of phase 1) ----
    for (int idx = t; idx < 208 * 16; idx += 512) {
        const int r = idx >> 4;
        const int c = idx & 15;
        CP_ASYNC16(sbase + OFF_BHI + r * PITCH_B + c * 16,
                   (const char*)g_w1hi + r * 256 + c * 16);
        CP_ASYNC16(sbase + OFF_BLO + r * PITCH_B + c * 16,
                   (const char*)g_w1lo + r * 256 + c * 16);
    }

    // ---- zero chunk pad rows (200..207 in all 8 sub-buffers) + tail ----
    {
        const uint4 z = make_uint4(0u, 0u, 0u, 0u);
        for (int idx = t; idx < 192; idx += 512) {
            const int buf = idx / 24;             // 0..7 (4 slots x hi/lo)
            const int rr  = (idx % 24) / 3;
            const int c   = idx % 3;
            *(uint4*)(smem + buf * 9984 + (200 + rr) * CH_PITCH + c * 16) = z;
        }
        for (int idx = t; idx < 48; idx += 512)   // tail pad 79872..80640
            *(uint4*)(smem + 79872 + idx * 16) = z;
        if (t < 128) b1s[t] = b1[t];
        if (t < 256) w2s[t] = W2[t];
    }

    // ---- stage chunks 0 and 1 (k = 0..31, all valid) ----
    for (int idx = t; idx < 1600; idx += 512) {
        const int ch = idx / 800;                 // 0 or 1
        const int r  = idx % 800;
        const int m = r >> 2, q = r & 3;
        float4 v = *(const float4*)&xb[m * C_IN + ch * 16 + 4 * q];
        uint2 hp, lp;
        split2(v.x, v.y, hp.x, lp.x);
        split2(v.z, v.w, hp.y, lp.y);
        *(uint2*)(smem + ch * CH_SLOT + m * CH_PITCH + q * 8) = hp;
        *(uint2*)(smem + ch * CH_SLOT + 9984 + m * CH_PITCH + q * 8) = lp;
    }
    CP_ASYNC_WAIT_ALL();
    __syncthreads();

    // ---- phase 1: xw = x @ W1, warp = (mp = w%7: m32) x (nh = w/7: n64) ----
    const int mp = (w < 14) ? (w % 7) : 0;
    const int nh = (w < 14) ? (w / 7) : 0;
    const int g  = lane >> 2;
    const int tg = lane & 3;

    float acc[2][8][4];
#pragma unroll
    for (int mt = 0; mt < 2; mt++)
#pragma unroll
        for (int n = 0; n < 8; n++) {
            acc[mt][n][0] = 0.f; acc[mt][n][1] = 0.f;
            acc[mt][n][2] = 0.f; acc[mt][n][3] = 0.f;
        }

    const uint32_t a_lane = (uint32_t)(32 * mp + (lane & 15)) * CH_PITCH
                          + (uint32_t)(lane >> 4) * 16;
    const uint32_t b_lane = (uint32_t)(lane & 15) * PITCH_B
                          + (uint32_t)(lane >> 4) * 16 + (uint32_t)nh * 128;

#pragma unroll 1
    for (int ks = 0; ks < 13; ks++) {
        // prefetch chunk ks+2 (distance 2): LDGs before MMA, stores after
        float4 v0, v1;
        const int has1 = (t < 288);
        if (ks <= 10) {
            const int k0n = 16 * (ks + 2);
            {
                const int m = t >> 2, q = t & 3, k = k0n + 4 * q;
                v0 = (k < 200) ? *(const float4*)&xb[m * C_IN + k]
                               : make_float4(0.f, 0.f, 0.f, 0.f);
            }
            if (has1) {
                const int idx = t + 512;
                const int m = idx >> 2, q = idx & 3, k = k0n + 4 * q;
                v1 = (k < 200) ? *(const float4*)&xb[m * C_IN + k]
                               : make_float4(0.f, 0.f, 0.f, 0.f);
            }
        }

        // MMA on slot ks & 3
        if (w < 14) {
            const uint32_t ch_hi = sbase + (uint32_t)(ks & 3) * CH_SLOT + a_lane;
            const uint32_t ch_lo = ch_hi + 9984;
            uint32_t ah[2][4], al[2][4];
            LDSM_X4(ah[0][0], ah[0][1], ah[0][2], ah[0][3], ch_hi);
            LDSM_X4(ah[1][0], ah[1][1], ah[1][2], ah[1][3], ch_hi + 16 * CH_PITCH);
            LDSM_X4(al[0][0], al[0][1], al[0][2], al[0][3], ch_lo);
            LDSM_X4(al[1][0], al[1][1], al[1][2], al[1][3], ch_lo + 16 * CH_PITCH);
            const uint32_t brow = sbase + OFF_BHI + b_lane + (uint32_t)ks * 16 * PITCH_B;
#pragma unroll
            for (int nbg = 0; nbg < 4; nbg++) {
                uint32_t h0, h1, h2, h3, l0, l1, l2, l3;
                LDSM_X4T(h0, h1, h2, h3, brow + (uint32_t)nbg * 32);
#pragma unroll
                for (int mt = 0; mt < 2; mt++) {
                    MMA16816(acc[mt][2 * nbg],     ah[mt][0], ah[mt][1], ah[mt][2], ah[mt][3], h0, h1);
                    MMA16816(acc[mt][2 * nbg + 1], ah[mt][0], ah[mt][1], ah[mt][2], ah[mt][3], h2, h3);
                    MMA16816(acc[mt][2 * nbg],     al[mt][0], al[mt][1], al[mt][2], al[mt][3], h0, h1);
                    MMA16816(acc[mt][2 * nbg + 1], al[mt][0], al[mt][1], al[mt][2], al[mt][3], h2, h3);
                }
                LDSM_X4T(l0, l1, l2, l3,
                         brow + (uint32_t)(OFF_BLO - OFF_BHI) + (uint32_t)nbg * 32);
#pragma unroll
                for (int mt = 0; mt < 2; mt++) {
                    MMA16816(acc[mt][2 * nbg],     ah[mt][0], ah[mt][1], ah[mt][2], ah[mt][3], l0, l1);
                    MMA16816(acc[mt][2 * nbg + 1], ah[mt][0], ah[mt][1], ah[mt][2], ah[mt][3], l2, l3);
                }
            }
        }

        // store prefetched chunk into slot (ks+2) & 3
        if (ks <= 10) {
            const uint32_t sofs = (uint32_t)((ks + 2) & 3) * CH_SLOT;
            {
                const int m = t >> 2, q = t & 3;
                uint2 hp, lp;
                split2(v0.x, v0.y, hp.x, lp.x);
                split2(v0.z, v0.w, hp.y, lp.y);
                *(uint2*)(smem + sofs + m * CH_PITCH + q * 8) = hp;
                *(uint2*)(smem + sofs + 9984 + m * CH_PITCH + q * 8) = lp;
            }
            if (has1) {
                const int idx = t + 512;
                const int m = idx >> 2, q = idx & 3;
                uint2 hp, lp;
                split2(v1.x, v1.y, hp.x, lp.x);
                split2(v1.z, v1.w, hp.y, lp.y);
                *(uint2*)(smem + sofs + m * CH_PITCH + q * 8) = hp;
                *(uint2*)(smem + sofs + 9984 + m * CH_PITCH + q * 8) = lp;
            }
        }
        if (ks & 1) __syncthreads();   // barrier every 2nd iteration suffices
    }
    __syncthreads();                   // protect W1 region before xw stores

    // ---- store xw fragments (bf16 hi/lo) into former W1 region ----
    if (w < 14) {
#pragma unroll
        for (int mt = 0; mt < 2; mt++) {
            const int ra = 32 * mp + 16 * mt + g;
            const int rb = ra + 8;
#pragma unroll
            for (int nt = 0; nt < 8; nt++) {
                const int f = 64 * nh + nt * 8 + tg * 2;
                uint32_t hp, lp;
                if (ra < 208) {
                    split2(acc[mt][nt][0], acc[mt][nt][1], hp, lp);
                    *(uint32_t*)(smem + OFF_BHI + ra * PITCH_B + f * 2) = hp;
                    *(uint32_t*)(smem + OFF_BLO + ra * PITCH_B + f * 2) = lp;
                }
                if (rb < 208) {
                    split2(acc[mt][nt][2], acc[mt][nt][3], hp, lp);
                    *(uint32_t*)(smem + OFF_BHI + rb * PITCH_B + f * 2) = hp;
                    *(uint32_t*)(smem + OFF_BLO + rb * PITCH_B + f * 2) = lp;
                }
            }
        }
    }

    // ---- phase 2 staging: adjA pads, adj (non-transposed) + row degrees ----
    {
        const uint4 z = make_uint4(0u, 0u, 0u, 0u);
        for (int r = t; r < 200; r += 512) {
            char* p = smem + OFF_A + r * PITCH_A;
            *(uint4*)(p + 400) = z;
            *(uint4*)(p + 416) = z;
        }
        for (int idx = t; idx < 8 * 27; idx += 512) {
            const int r = 200 + idx / 27;
            const int c = idx % 27;
            *(uint4*)(smem + OFF_A + r * PITCH_A + c * 16) = z;
        }
        for (int i = w; i < N_NODE; i += 16) {
            const int* row = &adj_b[i * N_NODE];
            char* dst = smem + OFF_A + i * PITCH_A;
            int rsum = 0;
#pragma unroll
            for (int c = 0; c < 7; c++) {
                const int j = lane + 32 * c;
                if (j < N_NODE) {
                    int v = row[j];
                    *(unsigned short*)(dst + j * 2) =
                        v ? (unsigned short)0x3F80u : (unsigned short)0u;
                    rsum += v;
                }
            }
#pragma unroll
            for (int off = 16; off; off >>= 1)
                rsum += __shfl_xor_sync(0xffffffffu, rsum, off);
            if (lane == 0) degs[i] = (float)rsum;
        }
    }
    __syncthreads();

    // ---- phase 2 MMA: agg = adjT @ xw (warps 0..13, m32 x n64) ----
    if (w < 14) {
#pragma unroll
        for (int mt = 0; mt < 2; mt++)
#pragma unroll
            for (int n = 0; n < 8; n++) {
                acc[mt][n][0] = 0.f; acc[mt][n][1] = 0.f;
                acc[mt][n][2] = 0.f; acc[mt][n][3] = 0.f;
            }

        const uint32_t a_row = (uint32_t)((lane & 7) + ((lane >> 4) << 3)) * PITCH_A;
        const uint32_t a0_base = sbase + OFF_A + a_row
            + (uint32_t)(32 * mp + ((lane >> 3) & 1) * 8) * 2;
        const uint32_t a1_base = a0_base + 32;
        const uint32_t bhi_base = sbase + OFF_BHI + b_lane;
        const uint32_t blo_base = sbase + OFF_BLO + b_lane;

#pragma unroll 1
        for (int ks = 0; ks < 13; ks++) {
            const uint32_t adelta = (uint32_t)ks * 16 * PITCH_A;
            uint32_t a[2][4];
            LDSM_X4T(a[0][0], a[0][1], a[0][2], a[0][3], a0_base + adelta);
            LDSM_X4T(a[1][0], a[1][1], a[1][2], a[1][3], a1_base + adelta);
            const uint32_t brow = (uint32_t)ks * 16 * PITCH_B;
#pragma unroll
            for (int nbg = 0; nbg < 4; nbg++) {
                uint32_t h0, h1, h2, h3, l0, l1, l2, l3;
                LDSM_X4T(h0, h1, h2, h3, bhi_base + brow + (uint32_t)nbg * 32);
#pragma unroll
                for (int mt = 0; mt < 2; mt++) {
                    MMA16816(acc[mt][2 * nbg],     a[mt][0], a[mt][1], a[mt][2], a[mt][3], h0, h1);
                    MMA16816(acc[mt][2 * nbg + 1], a[mt][0], a[mt][1], a[mt][2], a[mt][3], h2, h3);
                }
                LDSM_X4T(l0, l1, l2, l3, blo_base + brow + (uint32_t)nbg * 32);
#pragma unroll
                for (int mt = 0; mt < 2; mt++) {
                    MMA16816(acc[mt][2 * nbg],     a[mt][0], a[mt][1], a[mt][2], a[mt][3], l0, l1);
                    MMA16816(acc[mt][2 * nbg + 1], a[mt][0], a[mt][1], a[mt][2], a[mt][3], l2, l3);
                }
            }
        }

        // ---- epilogue ----
        const float c1x = 1.f + *eps1p;
        const float c2x = 1.f + *eps2p;

        float s0 = 0.f, s1 = 0.f;
#pragma unroll
        for (int mt = 0; mt < 2; mt++) {
#pragma unroll
            for (int half = 0; half < 2; half++) {
                const int j = 32 * mp + 16 * mt + g + half * 8;
                const int jc = (j < N_NODE) ? j : (N_NODE - 1);
                float p0 = 0.f, p1 = 0.f;
#pragma unroll
                for (int nt = 0; nt < 8; nt++) {
                    const int f = 64 * nh + nt * 8 + tg * 2;
                    uint32_t hv = *(uint32_t*)(smem + OFF_BHI + jc * PITCH_B + f * 2);
                    uint32_t lv = *(uint32_t*)(smem + OFF_BLO + jc * PITCH_B + f * 2);
                    float x0 = __uint_as_float(hv << 16) + __uint_as_float(lv << 16);
                    float x1 = __uint_as_float(hv & 0xFFFF0000u)
                             + __uint_as_float(lv & 0xFFFF0000u);
                    float a0 = acc[mt][nt][2 * half + 0];
                    float a1 = acc[mt][nt][2 * half + 1];
                    float h0 = fmaxf(fmaf(c1x, x0, a0) + b1s[f], 0.f);
                    float h1 = fmaxf(fmaf(c1x, x1, a1) + b1s[f + 1], 0.f);
                    p0 += h0 * w2s[f * 2]     + h1 * w2s[(f + 1) * 2];
                    p1 += h0 * w2s[f * 2 + 1] + h1 * w2s[(f + 1) * 2 + 1];
                }
                float wj = (j < N_NODE) ? (c2x + degs[jc]) : 0.f;
                s0 += p0 * wj;
                s1 += p1 * wj;
            }
        }
#pragma unroll
        for (int off = 1; off <= 16; off <<= 1) {
            s0 += __shfl_xor_sync(0xffffffffu, s0, off);
            s1 += __shfl_xor_sync(0xffffffffu, s1, off);
        }
        if (lane == 0) { wsum[w * 2 + 0] = s0; wsum[w * 2 + 1] = s1; }
    }
    __syncthreads();

    if (t < 2) {
        float s = 0.f;
#pragma unroll
        for (int q = 0; q < 14; q++) s += wsum[q * 2 + t];
        out[b * 2 + t] = s * (1.f / N_NODE) + b2[t];
    }
}

// ---------------------------------------------------------------------------
extern "C" void kernel_launch(void* const* d_in, const int* in_sizes, int n_in,
                              void* d_out, int out_size)
{
    const float* x    = (const float*)d_in[0];   // [512,200,200]
    const int*   adj  = (const int*)  d_in[1];   // [512,200,200]
    const float* W1   = (const float*)d_in[2];   // [200,128]
    const float* b1   = (const float*)d_in[3];   // [128]
    const float* W2   = (const float*)d_in[4];   // [128,2]
    const float* b2   = (const float*)d_in[5];   // [2]
    const float* eps1 = (const float*)d_in[6];
    const float* eps2 = (const float*)d_in[7];
    float* out = (float*)d_out;                  // [512,2]

    cudaFuncSetAttribute(gin_fused_all_kernel,
                         cudaFuncAttributeMaxDynamicSharedMemorySize, SMEM_TOTAL);

    split_w1_kernel<<<(208 * HIDDEN + 255) / 256, 256>>>(W1);
    gin_fused_all_kernel<<<BATCH, 512, SMEM_TOTAL>>>(x, adj, b1, W2, b2,
                                                     eps1, eps2, out);
}